// round 12
// baseline (speedup 1.0000x reference)
#include <cuda_runtime.h>

#define S_LEN 8192
#define DD 64
#define NBH 32            // B*H = 4*8
#define NSPLIT 16
#define CHUNK (S_LEN / NSPLIT)   // 512
#define TS 32             // rows per staged tile in k1
#define PART_KV 4096
#define PART_STRIDE 4160  // 64*64 KV + 64 ksum

__device__ float g_part[NBH * NSPLIT * PART_STRIDE];
__device__ float g_kv[NBH * PART_KV];
__device__ float g_ksum[NBH * DD];

typedef unsigned long long u64;

// phi(x) = elu(x)+1 = x>0 ? x+1 : exp(x)
__device__ __forceinline__ float phi(float x) {
    return x > 0.f ? x + 1.f : __expf(x);
}

// packed fp32x2 FMA: d = a*b + d (elementwise) — 2 FLOPs per issue slot
__device__ __forceinline__ void fma2(u64& d, u64 a, u64 b) {
    asm("fma.rn.f32x2 %0, %1, %2, %0;" : "+l"(d) : "l"(a), "l"(b));
}
__device__ __forceinline__ u64 dup2(float x) {
    u64 r;
    asm("mov.b64 %0, {%1, %1};" : "=l"(r) : "f"(x));
    return r;
}
__device__ __forceinline__ float2 unpack2(u64 v) {
    float2 r;
    asm("mov.b64 {%0, %1}, %2;" : "=f"(r.x), "=f"(r.y) : "l"(v));
    return r;
}

// ---------------------------------------------------------------------------
// Mask storage self-detection. The reference produces jnp.bool_ masks; the
// harness may transfer them as int32, float32, or raw bytes. Scan the first
// 128 words (512 bytes — in-bounds under every layout: byte layout needs
// 32768 B minimum) and classify. Misclassification prob with random 0/1
// masks ~ 2^-384.
//   mode 0: int32 (0/1 words)   mode 1: float32 (0f/1f words)   mode 2: bytes
// ---------------------------------------------------------------------------
__device__ __forceinline__ int mask_mode(const void* m) {
    const unsigned* w = (const unsigned*)m;
    bool i32 = true, f32 = true;
#pragma unroll 8
    for (int i = 0; i < 128; i++) {
        unsigned x = w[i];
        i32 &= (x <= 1u);
        f32 &= (x == 0u || x == 0x3F800000u);
    }
    return i32 ? 0 : (f32 ? 1 : 2);
}
__device__ __forceinline__ float mval(const void* m, long s, int mode) {
    if (mode == 0) return ((const int*)m)[s] ? 1.f : 0.f;
    if (mode == 1) return ((const float*)m)[s] != 0.f ? 1.f : 0.f;
    return ((const unsigned char*)m)[s] ? 1.f : 0.f;
}

// Transposed-q SMEM layout with XOR swizzle, conflict-free column writes:
// word index for logical (d, r):  d*64 + (r ^ (((d>>2)&15)<<1))
// mask is even -> preserves (even r, even r+1) pair contiguity + 8B alignment,
// so the GEMM reads (q[r],q[r+1]) as one LDS.64.
#define QT_IDX(d, r) (((d) << 6) + ((r) ^ ((((d) >> 2) & 15) << 1)))

// ---------------------------------------------------------------------------
// Kernel 1: partial KV[64][64] and ksum[64] per (bh, split).
// 256 threads as 16x16 grid; thread tile 4 rows (d of ke) x 4 cols (c of ve),
// packed as 2 row-pairs x 4 cols of f32x2.
// ---------------------------------------------------------------------------
__global__ void __launch_bounds__(256) k1_partial(
    const float* __restrict__ K, const float* __restrict__ V,
    const void* __restrict__ kvm)
{
    const int bh = blockIdx.x;
    const int split = blockIdx.y;
    const int b = bh >> 3;            // H = 8
    const int tid = threadIdx.x;
    const int i = tid >> 4;           // row group 0..15
    const int j = tid & 15;           // col group 0..15

    __shared__ __align__(16) float kbuf[TS][DD];
    __shared__ __align__(16) float vbuf[TS][DD];
    __shared__ __align__(16) float ksum_sh[16][DD];

    const int mmode = mask_mode(kvm);

    u64 acc[2][4];
#pragma unroll
    for (int rp = 0; rp < 2; rp++)
#pragma unroll
        for (int c = 0; c < 4; c++) acc[rp][c] = 0ull;
    float4 ksp = make_float4(0.f, 0.f, 0.f, 0.f);

    const long base = (long)bh * S_LEN;
    const int s0 = split * CHUNK;
    const long mbase = (long)b * S_LEN;

    for (int t = 0; t < CHUNK; t += TS) {
#pragma unroll
        for (int it = 0; it < 2; it++) {
            int idx = tid + it * 256;        // 0..511
            int row = idx >> 4;              // 0..31
            int c4 = (idx & 15) << 2;        // 0..60
            int s = s0 + t + row;
            float m = mval(kvm, mbase + s, mmode);
            float4 kr = *(const float4*)(K + (base + s) * DD + c4);
            float4 vr = *(const float4*)(V + (base + s) * DD + c4);
            float4 ke = make_float4(phi(kr.x) * m, phi(kr.y) * m,
                                    phi(kr.z) * m, phi(kr.w) * m);
            float4 ve = make_float4(vr.x * m, vr.y * m, vr.z * m, vr.w * m);
            *(float4*)&kbuf[row][c4] = ke;
            *(float4*)&vbuf[row][c4] = ve;
            ksp.x += ke.x; ksp.y += ke.y; ksp.z += ke.z; ksp.w += ke.w;
        }
        __syncthreads();
#pragma unroll
        for (int s = 0; s < TS; s++) {
            const u64* kp = (const u64*)&kbuf[s][i << 2];
            u64 ka0 = kp[0], ka1 = kp[1];    // pairs (4i,4i+1), (4i+2,4i+3)
            float4 vv = *(const float4*)&vbuf[s][j << 2];
            u64 b0 = dup2(vv.x), b1 = dup2(vv.y);
            u64 b2 = dup2(vv.z), b3 = dup2(vv.w);
            fma2(acc[0][0], ka0, b0); fma2(acc[0][1], ka0, b1);
            fma2(acc[0][2], ka0, b2); fma2(acc[0][3], ka0, b3);
            fma2(acc[1][0], ka1, b0); fma2(acc[1][1], ka1, b1);
            fma2(acc[1][2], ka1, b2); fma2(acc[1][3], ka1, b3);
        }
        __syncthreads();
    }

    float* outp = g_part + ((long)bh * NSPLIT + split) * PART_STRIDE;
#pragma unroll
    for (int rp = 0; rp < 2; rp++) {
        float2 c0 = unpack2(acc[rp][0]);
        float2 c1 = unpack2(acc[rp][1]);
        float2 c2 = unpack2(acc[rp][2]);
        float2 c3 = unpack2(acc[rp][3]);
        int r0 = (i << 2) + (rp << 1);
        *(float4*)(outp + r0 * DD + (j << 2)) = make_float4(c0.x, c1.x, c2.x, c3.x);
        *(float4*)(outp + (r0 + 1) * DD + (j << 2)) = make_float4(c0.y, c1.y, c2.y, c3.y);
    }
    *(float4*)&ksum_sh[i][j << 2] = ksp;
    __syncthreads();
    if (tid < DD) {
        float s = 0.f;
#pragma unroll
        for (int g = 0; g < 16; g++) s += ksum_sh[g][tid];
        outp[PART_KV + tid] = s;
    }
}

// ---------------------------------------------------------------------------
// Kernel 2: reduce 16 split-partials -> KV, ksum per bh. Fixed order.
// ---------------------------------------------------------------------------
__global__ void k2_reduce()
{
    int bh = blockIdx.x;
    const float* p = g_part + (long)bh * NSPLIT * PART_STRIDE;
    for (int e = threadIdx.x; e < PART_STRIDE; e += blockDim.x) {
        float s = 0.f;
#pragma unroll
        for (int sp = 0; sp < NSPLIT; sp++) s += p[sp * PART_STRIDE + e];
        if (e < PART_KV) g_kv[bh * PART_KV + e] = s;
        else             g_ksum[bh * DD + (e - PART_KV)] = s;
    }
}

// ---------------------------------------------------------------------------
// Kernel 3: out[l] = (phi(q)[l] @ KV) / (phi(q)[l] . ksum + 1e-6)
// Block: 256 rows of one bh (4 tiles of 64). KV resident in SMEM.
// Warp w covers rows w*8..w*8+7; lane covers cols 2*lane, 2*lane+1.
// Accumulators packed along row-pairs (f32x2); q pairs read via QT_IDX LDS.64.
// ---------------------------------------------------------------------------
__global__ void __launch_bounds__(256) k3_out(
    const float* __restrict__ Q, const void* __restrict__ qm,
    float* __restrict__ O)
{
    const int bh = blockIdx.y;
    const int b = bh >> 3;
    const int chunk = blockIdx.x;     // 0..31, 256 rows each
    const int tid = threadIdx.x;
    const int warp = tid >> 5;
    const int lane = tid & 31;

    __shared__ __align__(16) float kvb[DD][DD];
    __shared__ __align__(16) float qbT[DD * DD];
    __shared__ __align__(16) float ksum_s[DD];
    __shared__ __align__(16) float dinv[DD];

    const int mmode = mask_mode(qm);

    {
        const float4* src = (const float4*)(g_kv + bh * PART_KV);
        float4* dst = (float4*)&kvb[0][0];
        for (int e = tid; e < 1024; e += 256) dst[e] = src[e];
        if (tid < DD) ksum_s[tid] = g_ksum[bh * DD + tid];
    }
    __syncthreads();

    const long base = (long)bh * S_LEN;
    const long mbase = (long)b * S_LEN;
    const int w8 = warp << 3;

    for (int tile = 0; tile < 4; tile++) {
        const int row0 = chunk * 256 + tile * 64;

        // Stage phi(q)*mask transposed (swizzled) + per-row denominator.
#pragma unroll
        for (int it = 0; it < 4; it++) {
            int idx = tid + it * 256;         // 0..1023
            int row = idx >> 4;               // 0..63
            int c4 = (idx & 15) << 2;         // 0..60
            int grow = row0 + row;
            float m = mval(qm, mbase + grow, mmode);
            float4 qr = *(const float4*)(Q + (base + grow) * DD + c4);
            float4 qe = make_float4(phi(qr.x) * m, phi(qr.y) * m,
                                    phi(qr.z) * m, phi(qr.w) * m);
            qbT[QT_IDX(c4 + 0, row)] = qe.x;
            qbT[QT_IDX(c4 + 1, row)] = qe.y;
            qbT[QT_IDX(c4 + 2, row)] = qe.z;
            qbT[QT_IDX(c4 + 3, row)] = qe.w;
            float4 ks = *(const float4*)&ksum_s[c4];
            float dp = qe.x * ks.x + qe.y * ks.y + qe.z * ks.z + qe.w * ks.w;
            dp += __shfl_xor_sync(0xffffffffu, dp, 1);
            dp += __shfl_xor_sync(0xffffffffu, dp, 2);
            dp += __shfl_xor_sync(0xffffffffu, dp, 4);
            dp += __shfl_xor_sync(0xffffffffu, dp, 8);
            if ((lane & 15) == 0) dinv[row] = 1.f / (dp + 1e-6f);
        }
        __syncthreads();

        u64 acc[4][2];
#pragma unroll
        for (int rp = 0; rp < 4; rp++) { acc[rp][0] = 0ull; acc[rp][1] = 0ull; }

#pragma unroll
        for (int d = 0; d < DD; d++) {
            float2 kv2 = *(const float2*)&kvb[d][lane << 1];
            u64 b0 = dup2(kv2.x), b1 = dup2(kv2.y);
#pragma unroll
            for (int rp = 0; rp < 4; rp++) {
                u64 a = *(const u64*)&qbT[QT_IDX(d, w8 + (rp << 1))];
                fma2(acc[rp][0], a, b0);
                fma2(acc[rp][1], a, b1);
            }
        }

#pragma unroll
        for (int rp = 0; rp < 4; rp++) {
            float2 p0 = unpack2(acc[rp][0]);   // (row r0, row r0+1) @ col c0
            float2 p1 = unpack2(acc[rp][1]);   // (row r0, row r0+1) @ col c1
            int r0 = w8 + (rp << 1);
            float dv0 = dinv[r0], dv1 = dinv[r0 + 1];
            long g0 = base + row0 + r0;
            *(float2*)(O + g0 * DD + (lane << 1)) =
                make_float2(p0.x * dv0, p1.x * dv0);
            *(float2*)(O + (g0 + 1) * DD + (lane << 1)) =
                make_float2(p0.y * dv1, p1.y * dv1);
        }
        __syncthreads();
    }
}

// ---------------------------------------------------------------------------
extern "C" void kernel_launch(void* const* d_in, const int* in_sizes, int n_in,
                              void* d_out, int out_size)
{
    const float* q = (const float*)d_in[0];
    const float* k = (const float*)d_in[1];
    const float* v = (const float*)d_in[2];
    const void* q_mask  = d_in[3];
    const void* kv_mask = d_in[4];
    float* out = (float*)d_out;

    k1_partial<<<dim3(NBH, NSPLIT), 256>>>(k, v, kv_mask);
    k2_reduce<<<NBH, 256>>>();
    k3_out<<<dim3(S_LEN / 256, NBH), 256>>>(q, q_mask, out);
}

// round 13
// speedup vs baseline: 1.7080x; 1.7080x over previous
#include <cuda_runtime.h>

#define S_LEN 8192
#define DD 64
#define NBH 32            // B*H = 4*8
#define NSPLIT 32
#define CHUNK (S_LEN / NSPLIT)   // 256
#define TS 32             // rows per staged tile in k1
#define KSTRIDE 68        // padded smem row stride (floats)
#define PART_KV 4096
#define PART_STRIDE 4160  // 64*64 KV + 64 ksum

__device__ float g_part[NBH * NSPLIT * PART_STRIDE];
__device__ float g_kv[NBH * PART_KV];
__device__ float g_ksum[NBH * DD];

typedef unsigned long long u64;
typedef unsigned int u32;

// phi(x) = elu(x)+1 = x>0 ? x+1 : exp(x)
__device__ __forceinline__ float phi(float x) {
    return x > 0.f ? x + 1.f : __expf(x);
}
__device__ __forceinline__ float4 phi4(float4 v) {
    return make_float4(phi(v.x), phi(v.y), phi(v.z), phi(v.w));
}

// packed fp32x2 FMA: d = a*b + d — 2 FLOPs per issue slot
__device__ __forceinline__ void fma2(u64& d, u64 a, u64 b) {
    asm("fma.rn.f32x2 %0, %1, %2, %0;" : "+l"(d) : "l"(a), "l"(b));
}
__device__ __forceinline__ u64 dup2(float x) {
    u64 r;
    asm("mov.b64 %0, {%1, %1};" : "=l"(r) : "f"(x));
    return r;
}
__device__ __forceinline__ float2 unpack2(u64 v) {
    float2 r;
    asm("mov.b64 {%0, %1}, %2;" : "=f"(r.x), "=f"(r.y) : "l"(v));
    return r;
}

// ---------------------------------------------------------------------------
// Mask storage self-detection (mode 0: int32, 1: float32, 2: bytes).
// ---------------------------------------------------------------------------
__device__ __forceinline__ int mask_mode(const void* m) {
    const unsigned* w = (const unsigned*)m;
    bool i32 = true, f32 = true;
#pragma unroll 8
    for (int i = 0; i < 128; i++) {
        unsigned x = w[i];
        i32 &= (x <= 1u);
        f32 &= (x == 0u || x == 0x3F800000u);
    }
    return i32 ? 0 : (f32 ? 1 : 2);
}
__device__ __forceinline__ float mval(const void* m, long s, int mode) {
    if (mode == 0) return ((const int*)m)[s] ? 1.f : 0.f;
    if (mode == 1) return ((const float*)m)[s] != 0.f ? 1.f : 0.f;
    return ((const unsigned char*)m)[s] ? 1.f : 0.f;
}

// Transposed-q swizzle: word index for logical (d, r): d*64 + (r ^ bits[2:6]).
// Low 2 bits of r preserved -> 4-row groups stay contiguous + 16B aligned, so
// the GEMM reads 4 consecutive compacted rows as one LDS.128.
#define QT_IDX(d, r) (((d) << 6) + ((r) ^ ((((d) >> 2) & 15) << 2)))

// ---------------------------------------------------------------------------
// Kernel 1: partial KV[64][64] and ksum[64] per (bh, split).
// 128 threads: rowg i=tid>>4 (8 d-rows each), colg j=tid&15 (4 v-cols each).
// Mask-compacted tiles of TS=32 rows; register prefetch of next tile.
// ---------------------------------------------------------------------------
__global__ void __launch_bounds__(128) k1_partial(
    const float* __restrict__ K, const float* __restrict__ V,
    const void* __restrict__ kvm)
{
    const int bh = blockIdx.x;
    const int split = blockIdx.y;
    const int b = bh >> 3;            // H = 8
    const int tid = threadIdx.x;
    const int i = tid >> 4;           // 0..7
    const int c4 = (tid & 15) << 2;   // 0..60

    __shared__ __align__(16) float kbuf[TS][KSTRIDE];
    __shared__ __align__(16) float vbuf[TS][KSTRIDE];
    __shared__ __align__(16) float ksum_sh[8][DD];
    __shared__ u32 bm_sh[8];

    const int mmode = mask_mode(kvm);
    const long base = (long)bh * S_LEN;
    const int s0 = split * CHUNK;
    const long mbase = (long)b * S_LEN;

    // Per-tile mask bitmaps for all 8 tiles (256 rows): warp w ballots rows
    // 32w..32w+31 (tile w) and 128+32w (tile w+4). Bit lane = row-in-tile.
    {
        float m0 = mval(kvm, mbase + s0 + tid, mmode);
        float m1 = mval(kvm, mbase + s0 + 128 + tid, mmode);
        u32 b0 = __ballot_sync(0xffffffffu, m0 != 0.f);
        u32 b1 = __ballot_sync(0xffffffffu, m1 != 0.f);
        if ((tid & 31) == 0) { bm_sh[tid >> 5] = b0; bm_sh[(tid >> 5) + 4] = b1; }
    }
    __syncthreads();
    u32 bm[8];
#pragma unroll
    for (int t = 0; t < 8; t++) bm[t] = bm_sh[t];

    u64 acc[4][4];
#pragma unroll
    for (int rp = 0; rp < 4; rp++)
#pragma unroll
        for (int c = 0; c < 4; c++) acc[rp][c] = 0ull;
    float4 ksp = make_float4(0.f, 0.f, 0.f, 0.f);

    // Prefetch tile 0 (masked rows only).
    float4 kr[4], vr[4];
#pragma unroll
    for (int it = 0; it < 4; it++) {
        int row = i + it * 8;
        if ((bm[0] >> row) & 1) {
            long g = (base + s0 + row) * DD + c4;
            kr[it] = *(const float4*)(K + g);
            vr[it] = *(const float4*)(V + g);
        }
    }

    for (int t = 0; t < 8; t++) {
        const u32 bmt = bm[t];
        const int count = __popc(bmt);
        const int pad = (count + 3) & ~3;

        // Stage compacted phi(k), v into smem.
#pragma unroll
        for (int it = 0; it < 4; it++) {
            int row = i + it * 8;
            if ((bmt >> row) & 1) {
                int dest = __popc(bmt & ((1u << row) - 1u));
                float4 ke = phi4(kr[it]);
                *(float4*)&kbuf[dest][c4] = ke;
                *(float4*)&vbuf[dest][c4] = vr[it];
                ksp.x += ke.x; ksp.y += ke.y; ksp.z += ke.z; ksp.w += ke.w;
            }
        }
        // Zero-pad rows count..pad-1 so the GEMM can step by 4.
        if (tid < (pad - count) * 16) {
            int r = count + (tid >> 4);
            float4 z = make_float4(0.f, 0.f, 0.f, 0.f);
            *(float4*)&kbuf[r][(tid & 15) << 2] = z;
            *(float4*)&vbuf[r][(tid & 15) << 2] = z;
        }
        __syncthreads();

        // Prefetch tile t+1 — retires under the GEMM below.
        if (t < 7) {
            u32 bn = bm[t + 1];
#pragma unroll
            for (int it = 0; it < 4; it++) {
                int row = i + it * 8;
                if ((bn >> row) & 1) {
                    long g = (base + s0 + (t + 1) * TS + row) * DD + c4;
                    kr[it] = *(const float4*)(K + g);
                    vr[it] = *(const float4*)(V + g);
                }
            }
        }

        // Outer-product GEMM over compacted rows.
        for (int s = 0; s < pad; s += 4) {
#pragma unroll
            for (int ss = 0; ss < 4; ss++) {
                const float* kp = &kbuf[s + ss][i << 3];
                ulonglong2 kA = *(const ulonglong2*)(kp);       // d-pairs (8i,8i+1),(8i+2,8i+3)
                ulonglong2 kB = *(const ulonglong2*)(kp + 4);   // (8i+4,..),(8i+6,..)
                float4 vv = *(const float4*)&vbuf[s + ss][c4];
                u64 b0 = dup2(vv.x), b1 = dup2(vv.y);
                u64 b2 = dup2(vv.z), b3 = dup2(vv.w);
                fma2(acc[0][0], kA.x, b0); fma2(acc[0][1], kA.x, b1);
                fma2(acc[0][2], kA.x, b2); fma2(acc[0][3], kA.x, b3);
                fma2(acc[1][0], kA.y, b0); fma2(acc[1][1], kA.y, b1);
                fma2(acc[1][2], kA.y, b2); fma2(acc[1][3], kA.y, b3);
                fma2(acc[2][0], kB.x, b0); fma2(acc[2][1], kB.x, b1);
                fma2(acc[2][2], kB.x, b2); fma2(acc[2][3], kB.x, b3);
                fma2(acc[3][0], kB.y, b0); fma2(acc[3][1], kB.y, b1);
                fma2(acc[3][2], kB.y, b2); fma2(acc[3][3], kB.y, b3);
            }
        }
        __syncthreads();
    }

    float* outp = g_part + ((long)bh * NSPLIT + split) * PART_STRIDE;
#pragma unroll
    for (int rp = 0; rp < 4; rp++) {
        float2 c0 = unpack2(acc[rp][0]);
        float2 c1 = unpack2(acc[rp][1]);
        float2 c2 = unpack2(acc[rp][2]);
        float2 c3 = unpack2(acc[rp][3]);
        int r0 = (i << 3) + (rp << 1);
        *(float4*)(outp + r0 * DD + c4) = make_float4(c0.x, c1.x, c2.x, c3.x);
        *(float4*)(outp + (r0 + 1) * DD + c4) = make_float4(c0.y, c1.y, c2.y, c3.y);
    }
    *(float4*)&ksum_sh[i][c4] = ksp;
    __syncthreads();
    if (tid < DD) {
        float s = 0.f;
#pragma unroll
        for (int g = 0; g < 8; g++) s += ksum_sh[g][tid];
        outp[PART_KV + tid] = s;
    }
}

// ---------------------------------------------------------------------------
// Kernel 2: reduce NSPLIT split-partials -> KV, ksum per bh. Fixed order.
// Grid (NBH, 8): each block owns a 520-element slice.
// ---------------------------------------------------------------------------
__global__ void k2_reduce()
{
    const int bh = blockIdx.x;
    const int sl = blockIdx.y;
    const float* p = g_part + (long)bh * NSPLIT * PART_STRIDE;
    const int e0 = sl * 520;
    const int e1 = e0 + 520;
    for (int e = e0 + threadIdx.x; e < e1; e += 256) {
        float s = 0.f;
#pragma unroll
        for (int sp = 0; sp < NSPLIT; sp++) s += p[(long)sp * PART_STRIDE + e];
        if (e < PART_KV) g_kv[bh * PART_KV + e] = s;
        else             g_ksum[bh * DD + (e - PART_KV)] = s;
    }
}

// ---------------------------------------------------------------------------
// Kernel 3: out[l] = (phi(q)[l] @ KV) / (phi(q)[l] . ksum + 1e-6)
// 128 threads; block owns 256 rows (4 tiles of 64), KV resident in smem.
// Mask-compacted q tiles (zero rows written directly in staging, GEMM over
// count rows, scatter via row_of[]); register prefetch of next q tile.
// Thread tile: 8 rows (i) x 4 cols (j); acc packed f32x2 along row pairs.
// ---------------------------------------------------------------------------
__global__ void __launch_bounds__(128) k3_out(
    const float* __restrict__ Q, const void* __restrict__ qm,
    float* __restrict__ O)
{
    const int bh = blockIdx.y;
    const int b = bh >> 3;
    const int chunk = blockIdx.x;     // 0..31, 256 rows each
    const int tid = threadIdx.x;
    const int i = tid >> 4;           // 0..7
    const int c4 = (tid & 15) << 2;
    const int lane = tid & 31;
    const int w = tid >> 5;

    __shared__ __align__(16) float kvb[DD][DD];
    __shared__ __align__(16) float qbT[DD * DD];
    __shared__ __align__(16) float ksum_s[DD];
    __shared__ float dinv[DD];
    __shared__ unsigned char row_of[DD];
    __shared__ u32 bm_sh[8];

    const int mmode = mask_mode(qm);
    const long base = (long)bh * S_LEN;
    const long mbase = (long)b * S_LEN;
    const int row0 = chunk * 256;

    {
        const float4* src = (const float4*)(g_kv + bh * PART_KV);
        float4* dst = (float4*)&kvb[0][0];
#pragma unroll
        for (int e = 0; e < 8; e++) dst[tid + e * 128] = src[tid + e * 128];
        if (tid < DD) ksum_s[tid] = g_ksum[bh * DD + tid];
        float m0 = mval(qm, mbase + row0 + tid, mmode);
        float m1 = mval(qm, mbase + row0 + 128 + tid, mmode);
        u32 b0 = __ballot_sync(0xffffffffu, m0 != 0.f);
        u32 b1 = __ballot_sync(0xffffffffu, m1 != 0.f);
        if (lane == 0) { bm_sh[w] = b0; bm_sh[w + 4] = b1; }
    }
    __syncthreads();
    u32 bml[4], bmh[4];
#pragma unroll
    for (int t = 0; t < 4; t++) { bml[t] = bm_sh[2 * t]; bmh[t] = bm_sh[2 * t + 1]; }

    // Prefetch tile 0 (masked rows only).
    float4 qr[8];
#pragma unroll
    for (int it = 0; it < 8; it++) {
        int row = i + it * 8;
        bool bit = row < 32 ? ((bml[0] >> row) & 1) : ((bmh[0] >> (row - 32)) & 1);
        if (bit) qr[it] = *(const float4*)(Q + (base + row0 + row) * DD + c4);
    }

    for (int t = 0; t < 4; t++) {
        const u32 lo = bml[t], hi = bmh[t];
        const int count = __popc(lo) + __popc(hi);
        const int trow0 = row0 + t * 64;

        // Stage compacted phi(q) transposed + denominator; zero-out unmasked rows.
#pragma unroll
        for (int it = 0; it < 8; it++) {
            int row = i + it * 8;
            bool bit = row < 32 ? ((lo >> row) & 1) : ((hi >> (row - 32)) & 1);
            float4 qe = bit ? phi4(qr[it]) : make_float4(0.f, 0.f, 0.f, 0.f);
            float4 ks = *(const float4*)&ksum_s[c4];
            float dp = qe.x * ks.x + qe.y * ks.y + qe.z * ks.z + qe.w * ks.w;
            dp += __shfl_xor_sync(0xffffffffu, dp, 1);
            dp += __shfl_xor_sync(0xffffffffu, dp, 2);
            dp += __shfl_xor_sync(0xffffffffu, dp, 4);
            dp += __shfl_xor_sync(0xffffffffu, dp, 8);
            if (bit) {
                int dest = row < 32 ? __popc(lo & ((1u << row) - 1u))
                                    : __popc(lo) + __popc(hi & ((1u << (row - 32)) - 1u));
                qbT[QT_IDX(c4 + 0, dest)] = qe.x;
                qbT[QT_IDX(c4 + 1, dest)] = qe.y;
                qbT[QT_IDX(c4 + 2, dest)] = qe.z;
                qbT[QT_IDX(c4 + 3, dest)] = qe.w;
                if ((lane & 15) == 0) {
                    dinv[dest] = 1.f / (dp + 1e-6f);
                    row_of[dest] = (unsigned char)row;
                }
            } else {
                *(float4*)(O + (base + trow0 + row) * DD + c4) =
                    make_float4(0.f, 0.f, 0.f, 0.f);
            }
        }
        __syncthreads();

        // Prefetch tile t+1 — retires under the GEMM below.
        if (t < 3) {
            u32 nlo = bml[t + 1], nhi = bmh[t + 1];
#pragma unroll
            for (int it = 0; it < 8; it++) {
                int row = i + it * 8;
                bool bit = row < 32 ? ((nlo >> row) & 1) : ((nhi >> (row - 32)) & 1);
                if (bit) qr[it] = *(const float4*)(Q + (base + trow0 + 64 + row) * DD + c4);
            }
        }

        // GEMM over compacted rows (warp covers compacted rows 16w..16w+15).
        if (w * 16 < count) {
            u64 acc[4][4];
#pragma unroll
            for (int rp = 0; rp < 4; rp++)
#pragma unroll
                for (int c = 0; c < 4; c++) acc[rp][c] = 0ull;

#pragma unroll
            for (int d = 0; d < DD; d++) {
                ulonglong2 qA = *(const ulonglong2*)&qbT[QT_IDX(d, i << 3)];
                ulonglong2 qB = *(const ulonglong2*)&qbT[QT_IDX(d, (i << 3) + 4)];
                float4 kv4 = *(const float4*)&kvb[d][c4];
                u64 b0 = dup2(kv4.x), b1 = dup2(kv4.y);
                u64 b2 = dup2(kv4.z), b3 = dup2(kv4.w);
                fma2(acc[0][0], qA.x, b0); fma2(acc[0][1], qA.x, b1);
                fma2(acc[0][2], qA.x, b2); fma2(acc[0][3], qA.x, b3);
                fma2(acc[1][0], qA.y, b0); fma2(acc[1][1], qA.y, b1);
                fma2(acc[1][2], qA.y, b2); fma2(acc[1][3], qA.y, b3);
                fma2(acc[2][0], qB.x, b0); fma2(acc[2][1], qB.x, b1);
                fma2(acc[2][2], qB.x, b2); fma2(acc[2][3], qB.x, b3);
                fma2(acc[3][0], qB.y, b0); fma2(acc[3][1], qB.y, b1);
                fma2(acc[3][2], qB.y, b2); fma2(acc[3][3], qB.y, b3);
            }

#pragma unroll
            for (int rp = 0; rp < 4; rp++) {
                int r0 = (i << 3) + (rp << 1);
                if (r0 < count) {
                    float2 c0 = unpack2(acc[rp][0]);
                    float2 c1 = unpack2(acc[rp][1]);
                    float2 c2 = unpack2(acc[rp][2]);
                    float2 c3 = unpack2(acc[rp][3]);
                    float dv0 = dinv[r0];
                    int or0 = row_of[r0];
                    *(float4*)(O + (base + trow0 + or0) * DD + c4) =
                        make_float4(c0.x * dv0, c1.x * dv0, c2.x * dv0, c3.x * dv0);
                    if (r0 + 1 < count) {
                        float dv1 = dinv[r0 + 1];
                        int or1 = row_of[r0 + 1];
                        *(float4*)(O + (base + trow0 + or1) * DD + c4) =
                            make_float4(c0.y * dv1, c1.y * dv1, c2.y * dv1, c3.y * dv1);
                    }
                }
            }
        }
        __syncthreads();
    }
}

// ---------------------------------------------------------------------------
extern "C" void kernel_launch(void* const* d_in, const int* in_sizes, int n_in,
                              void* d_out, int out_size)
{
    const float* q = (const float*)d_in[0];
    const float* k = (const float*)d_in[1];
    const float* v = (const float*)d_in[2];
    const void* q_mask  = d_in[3];
    const void* kv_mask = d_in[4];
    float* out = (float*)d_out;

    k1_partial<<<dim3(NBH, NSPLIT), 128>>>(k, v, kv_mask);
    k2_reduce<<<dim3(NBH, 8), 256>>>();
    k3_out<<<dim3(S_LEN / 256, NBH), 128>>>(q, q_mask, out);
}